// round 1
// baseline (speedup 1.0000x reference)
#include <cuda_runtime.h>
#include <math.h>

// Problem constants
#define BB   4
#define SS   2048
#define DD   1024
#define HH   16
#define HD   64
#define MR   (BB * SS)          // 8192 rows

// ---------------------------------------------------------------------------
// Scratch (device globals; no allocation allowed)
// ---------------------------------------------------------------------------
__device__ float g_q[8388608];      // [MR, DD]
__device__ float g_k[8388608];
__device__ float g_v[8388608];
__device__ float g_attn[8388608];

// ---------------------------------------------------------------------------
// GEMM: C[M,N] = A[M,K] @ B[N,K]^T   (row-major A, row-major weight [out,in])
// M=8192, N=1024, K=1024. Tile 128x128x16, 256 threads, 8x8 per thread.
// ---------------------------------------------------------------------------
#define GBM 128
#define GBN 128
#define GBK 16
#define GPAD 4

__global__ __launch_bounds__(256)
void gemm_nt_kernel(const float* __restrict__ A,
                    const float* __restrict__ Bw,
                    float* __restrict__ C)
{
    const int M = MR, N = DD, K = DD;
    __shared__ float sA[GBK][GBM + GPAD];
    __shared__ float sB[GBK][GBN + GPAD];

    const int tid = threadIdx.x;
    const int tx  = tid & 15;        // 0..15 -> n
    const int ty  = tid >> 4;        // 0..15 -> m
    const int bm  = blockIdx.x * GBM;
    const int bn  = blockIdx.y * GBN;

    const int lr = tid >> 2;          // 0..63
    const int lc = (tid & 3) * 4;     // 0,4,8,12

    float acc[8][8];
#pragma unroll
    for (int i = 0; i < 8; i++)
#pragma unroll
        for (int j = 0; j < 8; j++) acc[i][j] = 0.f;

    for (int kt = 0; kt < K; kt += GBK) {
        // Load A tile (transpose into smem: sA[k][m])
#pragma unroll
        for (int p = 0; p < 2; p++) {
            int row = lr + p * 64;
            float4 v = *(const float4*)(A + (size_t)(bm + row) * K + kt + lc);
            sA[lc + 0][row] = v.x;
            sA[lc + 1][row] = v.y;
            sA[lc + 2][row] = v.z;
            sA[lc + 3][row] = v.w;
        }
        // Load B tile (weight rows are output features; sB[k][n])
#pragma unroll
        for (int p = 0; p < 2; p++) {
            int row = lr + p * 64;
            float4 v = *(const float4*)(Bw + (size_t)(bn + row) * K + kt + lc);
            sB[lc + 0][row] = v.x;
            sB[lc + 1][row] = v.y;
            sB[lc + 2][row] = v.z;
            sB[lc + 3][row] = v.w;
        }
        __syncthreads();

#pragma unroll
        for (int k = 0; k < GBK; k++) {
            float4 a0 = *(const float4*)&sA[k][ty * 8];
            float4 a1 = *(const float4*)&sA[k][ty * 8 + 4];
            float4 b0 = *(const float4*)&sB[k][tx * 8];
            float4 b1 = *(const float4*)&sB[k][tx * 8 + 4];
            float ar[8] = {a0.x, a0.y, a0.z, a0.w, a1.x, a1.y, a1.z, a1.w};
            float br[8] = {b0.x, b0.y, b0.z, b0.w, b1.x, b1.y, b1.z, b1.w};
#pragma unroll
            for (int i = 0; i < 8; i++)
#pragma unroll
                for (int j = 0; j < 8; j++)
                    acc[i][j] = fmaf(ar[i], br[j], acc[i][j]);
        }
        __syncthreads();
    }

    // Store
#pragma unroll
    for (int i = 0; i < 8; i++) {
        float* crow = C + (size_t)(bm + ty * 8 + i) * N + bn + tx * 8;
        float4 o0 = make_float4(acc[i][0], acc[i][1], acc[i][2], acc[i][3]);
        float4 o1 = make_float4(acc[i][4], acc[i][5], acc[i][6], acc[i][7]);
        *(float4*)(crow)     = o0;
        *(float4*)(crow + 4) = o1;
    }
}

// ---------------------------------------------------------------------------
// Flash-style causal attention (fp32).
// grid = (S/64, B*H). One CTA handles a 64-row Q block for one (b,h).
// Streams 64-row KV blocks up to the diagonal; online softmax; O in regs.
// ---------------------------------------------------------------------------
#define AQ 64
#define AKV 64

// dynamic smem layout (floats):
//  sQ  [HD][AQ+4]   transposed: [hd][q]        4352
//  sK  [HD][AKV+4]  transposed: [hd][kv]       4352
//  sV  [AKV][HD+4]  [kv][hd]                   4352
//  sS  [AQ][AKV+1]  scores/probs               4160
//  sm, sl, ssc [AQ] each                        192
#define OFF_Q   0
#define OFF_K   (OFF_Q + HD * (AQ + 4))
#define OFF_V   (OFF_K + HD * (AKV + 4))
#define OFF_S   (OFF_V + AKV * (HD + 4))
#define OFF_M   (OFF_S + AQ * (AKV + 1))
#define OFF_L   (OFF_M + AQ)
#define OFF_SC  (OFF_L + AQ)
#define ATTN_SMEM_FLOATS (OFF_SC + AQ)
#define ATTN_SMEM_BYTES  (ATTN_SMEM_FLOATS * 4)

__global__ __launch_bounds__(256)
void attn_kernel(const float* __restrict__ Q,
                 const float* __restrict__ Kk,
                 const float* __restrict__ V,
                 float* __restrict__ O)
{
    extern __shared__ float smem[];
    float* sQ  = smem + OFF_Q;   // [HD][AQ+4]
    float* sK  = smem + OFF_K;   // [HD][AKV+4]
    float* sV  = smem + OFF_V;   // [AKV][HD+4]
    float* sS  = smem + OFF_S;   // [AQ][AKV+1]
    float* sm  = smem + OFF_M;
    float* sl  = smem + OFF_L;
    float* ssc = smem + OFF_SC;

    const int qb = blockIdx.x;           // 0..31
    const int bh = blockIdx.y;           // 0..63
    const int b  = bh / HH;
    const int h  = bh % HH;
    const size_t base = (size_t)b * SS * DD + (size_t)h * HD;   // row stride DD

    const int tid = threadIdx.x;
    const int tx  = tid & 15;            // col group
    const int ty  = tid >> 4;            // row group (q rows ty*4..+3)

    // Load Q block transposed: sQ[hd][q]
    {
        int row = tid >> 2;                  // 0..63 (q)
#pragma unroll
        for (int p = 0; p < 4; p++) {
            int col = (tid & 3) * 4 + p * 16;  // hd
            float4 v = *(const float4*)(Q + base + (size_t)(qb * AQ + row) * DD + col);
            sQ[(col + 0) * (AQ + 4) + row] = v.x;
            sQ[(col + 1) * (AQ + 4) + row] = v.y;
            sQ[(col + 2) * (AQ + 4) + row] = v.z;
            sQ[(col + 3) * (AQ + 4) + row] = v.w;
        }
    }
    if (tid < AQ) { sm[tid] = -INFINITY; sl[tid] = 0.f; }

    float oacc[4][4];
#pragma unroll
    for (int i = 0; i < 4; i++)
#pragma unroll
        for (int j = 0; j < 4; j++) oacc[i][j] = 0.f;

    __syncthreads();

    for (int jb = 0; jb <= qb; jb++) {
        // Load K (transposed) and V blocks
        {
            int row = tid >> 2;                // kv row
#pragma unroll
            for (int p = 0; p < 4; p++) {
                int col = (tid & 3) * 4 + p * 16;  // hd
                float4 kv4 = *(const float4*)(Kk + base + (size_t)(jb * AKV + row) * DD + col);
                sK[(col + 0) * (AKV + 4) + row] = kv4.x;
                sK[(col + 1) * (AKV + 4) + row] = kv4.y;
                sK[(col + 2) * (AKV + 4) + row] = kv4.z;
                sK[(col + 3) * (AKV + 4) + row] = kv4.w;
                float4 vv4 = *(const float4*)(V + base + (size_t)(jb * AKV + row) * DD + col);
                *(float4*)&sV[row * (HD + 4) + col] = vv4;
            }
        }
        __syncthreads();

        // S = Q K^T * scale, thread computes 4x4 (q rows ty*4.., kv cols tx*4..)
        float s[4][4];
#pragma unroll
        for (int i = 0; i < 4; i++)
#pragma unroll
            for (int j = 0; j < 4; j++) s[i][j] = 0.f;

        for (int d0 = 0; d0 < HD; d0++) {
            float4 aq = *(const float4*)&sQ[d0 * (AQ + 4) + ty * 4];
            float4 bk = *(const float4*)&sK[d0 * (AKV + 4) + tx * 4];
            float ar[4] = {aq.x, aq.y, aq.z, aq.w};
            float br[4] = {bk.x, bk.y, bk.z, bk.w};
#pragma unroll
            for (int i = 0; i < 4; i++)
#pragma unroll
                for (int j = 0; j < 4; j++)
                    s[i][j] = fmaf(ar[i], br[j], s[i][j]);
        }
        const float scale = 0.125f;   // 1/sqrt(64)
#pragma unroll
        for (int i = 0; i < 4; i++) {
            int qg = qb * AQ + ty * 4 + i;
#pragma unroll
            for (int j = 0; j < 4; j++) {
                int kg = jb * AKV + tx * 4 + j;
                float val = s[i][j] * scale;
                if (kg > qg) val = -INFINITY;
                sS[(ty * 4 + i) * (AKV + 1) + (tx * 4 + j)] = val;
            }
        }
        __syncthreads();

        // Online softmax per q row (one thread per row)
        if (tid < AQ) {
            float mold = sm[tid];
            float bmax = -INFINITY;
            float* srow = sS + tid * (AKV + 1);
#pragma unroll 8
            for (int c = 0; c < AKV; c++) bmax = fmaxf(bmax, srow[c]);
            float mnew = fmaxf(mold, bmax);
            float scl  = __expf(mold - mnew);   // 0 when mold=-inf
            float sum  = 0.f;
#pragma unroll 8
            for (int c = 0; c < AKV; c++) {
                float p = __expf(srow[c] - mnew);
                srow[c] = p;
                sum += p;
            }
            sl[tid]  = sl[tid] * scl + sum;
            sm[tid]  = mnew;
            ssc[tid] = scl;
        }
        __syncthreads();

        // Rescale O and accumulate P @ V (q rows ty*4.., hd cols tx*4..)
        float scr[4];
#pragma unroll
        for (int i = 0; i < 4; i++) scr[i] = ssc[ty * 4 + i];
#pragma unroll
        for (int i = 0; i < 4; i++)
#pragma unroll
            for (int j = 0; j < 4; j++) oacc[i][j] *= scr[i];

        for (int kv = 0; kv < AKV; kv++) {
            float pr[4];
#pragma unroll
            for (int i = 0; i < 4; i++) pr[i] = sS[(ty * 4 + i) * (AKV + 1) + kv];
            float4 vv = *(const float4*)&sV[kv * (HD + 4) + tx * 4];
            float vr[4] = {vv.x, vv.y, vv.z, vv.w};
#pragma unroll
            for (int i = 0; i < 4; i++)
#pragma unroll
                for (int j = 0; j < 4; j++)
                    oacc[i][j] = fmaf(pr[i], vr[j], oacc[i][j]);
        }
        __syncthreads();   // protect sK/sV/sS before next iteration's loads
    }

    // Epilogue: divide by l, write out
    float linv[4];
#pragma unroll
    for (int i = 0; i < 4; i++) linv[i] = 1.0f / sl[ty * 4 + i];
#pragma unroll
    for (int i = 0; i < 4; i++) {
        int qg = qb * AQ + ty * 4 + i;
        float4 o = make_float4(oacc[i][0] * linv[i], oacc[i][1] * linv[i],
                               oacc[i][2] * linv[i], oacc[i][3] * linv[i]);
        *(float4*)(O + base + (size_t)qg * DD + tx * 4) = o;
    }
}

// ---------------------------------------------------------------------------
// Launch
// ---------------------------------------------------------------------------
extern "C" void kernel_launch(void* const* d_in, const int* in_sizes, int n_in,
                              void* d_out, int out_size)
{
    const float* x  = (const float*)d_in[0];
    const float* wq = (const float*)d_in[1];
    const float* wk = (const float*)d_in[2];
    const float* wv = (const float*)d_in[3];
    const float* wo = (const float*)d_in[4];
    float* out = (float*)d_out;

    float *q, *k, *v, *att;
    cudaGetSymbolAddress((void**)&q,   g_q);
    cudaGetSymbolAddress((void**)&k,   g_k);
    cudaGetSymbolAddress((void**)&v,   g_v);
    cudaGetSymbolAddress((void**)&att, g_attn);

    cudaFuncSetAttribute(attn_kernel, cudaFuncAttributeMaxDynamicSharedMemorySize,
                         ATTN_SMEM_BYTES);

    dim3 ggrid(MR / GBM, DD / GBN);   // (64, 8)
    dim3 gblk(256);

    gemm_nt_kernel<<<ggrid, gblk>>>(x, wq, q);
    gemm_nt_kernel<<<ggrid, gblk>>>(x, wk, k);
    gemm_nt_kernel<<<ggrid, gblk>>>(x, wv, v);

    dim3 agrid(SS / AQ, BB * HH);     // (32, 64)
    attn_kernel<<<agrid, 256, ATTN_SMEM_BYTES>>>(q, k, v, att);

    gemm_nt_kernel<<<ggrid, gblk>>>(att, wo, out);
}

// round 3
// speedup vs baseline: 1.4176x; 1.4176x over previous
#include <cuda_runtime.h>
#include <cuda_bf16.h>
#include <math.h>
#include <stdint.h>

// Problem constants
#define BB   4
#define SS   2048
#define DD   1024
#define HH   16
#define HD   64
#define MR   (BB * SS)          // 8192 rows

// ---------------------------------------------------------------------------
// Scratch (device globals; no allocation allowed)
// ---------------------------------------------------------------------------
__device__ float g_q[8388608];      // [MR, DD]
__device__ float g_k[8388608];
__device__ float g_v[8388608];
__device__ float g_attn[8388608];

// ---------------------------------------------------------------------------
// Warp-MMA helpers (plain sm_103-legal PTX: ldmatrix + mma.sync, sm_80+)
// ---------------------------------------------------------------------------
__device__ __forceinline__ uint32_t smem_u32(const void* p) {
    uint32_t a;
    asm("{ .reg .u64 t; cvta.to.shared.u64 t, %1; cvt.u32.u64 %0, t; }" : "=r"(a) : "l"(p));
    return a;
}

__device__ __forceinline__ void ldmx4(uint32_t* r, uint32_t addr) {
    asm volatile("ldmatrix.sync.aligned.m8n8.x4.shared.b16 {%0,%1,%2,%3}, [%4];"
                 : "=r"(r[0]), "=r"(r[1]), "=r"(r[2]), "=r"(r[3]) : "r"(addr));
}

__device__ __forceinline__ void mma_bf16(float* c, const uint32_t* a,
                                         uint32_t b0, uint32_t b1) {
    asm volatile(
        "mma.sync.aligned.m16n8k16.row.col.f32.bf16.bf16.f32 "
        "{%0,%1,%2,%3}, {%4,%5,%6,%7}, {%8,%9}, {%0,%1,%2,%3};"
        : "+f"(c[0]), "+f"(c[1]), "+f"(c[2]), "+f"(c[3])
        : "r"(a[0]), "r"(a[1]), "r"(a[2]), "r"(a[3]), "r"(b0), "r"(b1));
}

// ---------------------------------------------------------------------------
// Split-bf16 HMMA GEMM: C[M,N] = A[M,K] @ Bw[N,K]^T, fp32 in/out.
// Each fp32 v = hi + lo (bf16); D += Ah*Bh + Ah*Bl + Al*Bh  (err ~1e-6).
// CTA tile 128x128, K-tile 32, 512 threads (4x4 warps, warp tile 32x32).
// ---------------------------------------------------------------------------
#define BKP 40                       // padded row: 32 bf16 + 8 pad (80 B)
#define TILE_E  (128 * BKP)          // 5120 bf16 per tile
#define STAGE_E (4 * TILE_E)         // Ah, Al, Bh, Bl
#define GEMM_SMEM (2 * STAGE_E * 2)  // bytes (81920)

__device__ __forceinline__ void split4(__nv_bfloat16* hi, __nv_bfloat16* lo, float4 v) {
    __nv_bfloat162 h01 = __floats2bfloat162_rn(v.x, v.y);
    __nv_bfloat162 h23 = __floats2bfloat162_rn(v.z, v.w);
    __nv_bfloat162 l01 = __floats2bfloat162_rn(v.x - __bfloat162float(h01.x),
                                               v.y - __bfloat162float(h01.y));
    __nv_bfloat162 l23 = __floats2bfloat162_rn(v.z - __bfloat162float(h23.x),
                                               v.w - __bfloat162float(h23.y));
    *reinterpret_cast<__nv_bfloat162*>(hi)     = h01;
    *reinterpret_cast<__nv_bfloat162*>(hi + 2) = h23;
    *reinterpret_cast<__nv_bfloat162*>(lo)     = l01;
    *reinterpret_cast<__nv_bfloat162*>(lo + 2) = l23;
}

__global__ __launch_bounds__(512)
void gemm_mma(const float* __restrict__ A, const float* __restrict__ Bw,
              float* __restrict__ C)
{
    extern __shared__ __align__(16) char smem_raw[];
    __nv_bfloat16* sm = reinterpret_cast<__nv_bfloat16*>(smem_raw);

    const int tid  = threadIdx.x;
    const int lane = tid & 31;
    const int wid  = tid >> 5;          // 0..15
    const int wm   = wid >> 2;          // warp row 0..3  (32 rows each)
    const int wn   = wid & 3;           // warp col 0..3  (32 cols each)
    const int bm   = blockIdx.x * 128;
    const int bn   = blockIdx.y * 128;

    // global load mapping: 4 threads per row, 8 floats each
    const int lr = tid >> 2;            // 0..127
    const int lc = (tid & 3) * 8;       // 0,8,16,24
    const float* Ag = A  + (size_t)(bm + lr) * DD + lc;
    const float* Bg = Bw + (size_t)(bn + lr) * DD + lc;

    float4 ra0, ra1, rb0, rb1;

    // ldmatrix lane addressing (bytes, relative to tile base)
    const uint32_t aoffB =
        (uint32_t)(((wm * 32 + (lane & 15)) * BKP + (lane >> 4) * 8) * 2);
    const uint32_t boffB =
        (uint32_t)(((wn * 32 + ((lane >> 4) << 3) + (lane & 7)) * BKP +
                    ((lane >> 3) & 1) * 8) * 2);

    const uint32_t smem_base = smem_u32(sm);

    float acc[2][4][4];
#pragma unroll
    for (int mt = 0; mt < 2; mt++)
#pragma unroll
        for (int nt = 0; nt < 4; nt++)
#pragma unroll
            for (int i = 0; i < 4; i++) acc[mt][nt][i] = 0.f;

    // ---- prologue: load + store K-tile 0 ----
    {
        const float* a = Ag; const float* b = Bg;
        ra0 = *(const float4*)a;       ra1 = *(const float4*)(a + 4);
        rb0 = *(const float4*)b;       rb1 = *(const float4*)(b + 4);
        __nv_bfloat16* s = sm;
        int o = lr * BKP + lc;
        split4(s + o,              s + TILE_E + o,     ra0);
        split4(s + o + 4,          s + TILE_E + o + 4, ra1);
        split4(s + 2*TILE_E + o,   s + 3*TILE_E + o,     rb0);
        split4(s + 2*TILE_E + o+4, s + 3*TILE_E + o + 4, rb1);
    }
    __syncthreads();

#pragma unroll 1
    for (int kt = 0; kt < 32; kt++) {
        const int buf = kt & 1;
        // issue next-tile global loads early
        if (kt + 1 < 32) {
            const float* a = Ag + (kt + 1) * 32;
            const float* b = Bg + (kt + 1) * 32;
            ra0 = *(const float4*)a;   ra1 = *(const float4*)(a + 4);
            rb0 = *(const float4*)b;   rb1 = *(const float4*)(b + 4);
        }

        // compute on buf
        const uint32_t tA_h = smem_base + buf * STAGE_E * 2;
        const uint32_t tA_l = tA_h + TILE_E * 2;
        const uint32_t tB_h = tA_h + 2 * TILE_E * 2;
        const uint32_t tB_l = tA_h + 3 * TILE_E * 2;
#pragma unroll
        for (int ks = 0; ks < 2; ks++) {
            const uint32_t kb = ks * 32;   // 16 bf16 = 32 bytes
            uint32_t ah[2][4], al[2][4], bh[2][4], bl[2][4];
#pragma unroll
            for (int mt = 0; mt < 2; mt++) {
                ldmx4(ah[mt], tA_h + aoffB + mt * (16 * BKP * 2) + kb);
                ldmx4(al[mt], tA_l + aoffB + mt * (16 * BKP * 2) + kb);
            }
#pragma unroll
            for (int nt2 = 0; nt2 < 2; nt2++) {
                ldmx4(bh[nt2], tB_h + boffB + nt2 * (16 * BKP * 2) + kb);
                ldmx4(bl[nt2], tB_l + boffB + nt2 * (16 * BKP * 2) + kb);
            }
#pragma unroll
            for (int mt = 0; mt < 2; mt++) {
#pragma unroll
                for (int nt2 = 0; nt2 < 2; nt2++) {
#pragma unroll
                    for (int h = 0; h < 2; h++) {
                        float* c = acc[mt][nt2 * 2 + h];
                        uint32_t b0h = bh[nt2][h * 2], b1h = bh[nt2][h * 2 + 1];
                        uint32_t b0l = bl[nt2][h * 2], b1l = bl[nt2][h * 2 + 1];
                        mma_bf16(c, ah[mt], b0h, b1h);
                        mma_bf16(c, ah[mt], b0l, b1l);
                        mma_bf16(c, al[mt], b0h, b1h);
                    }
                }
            }
        }

        if (kt + 1 < 32) {
            __nv_bfloat16* s = sm + (1 - buf) * STAGE_E;
            int o = lr * BKP + lc;
            split4(s + o,              s + TILE_E + o,     ra0);
            split4(s + o + 4,          s + TILE_E + o + 4, ra1);
            split4(s + 2*TILE_E + o,   s + 3*TILE_E + o,     rb0);
            split4(s + 2*TILE_E + o+4, s + 3*TILE_E + o + 4, rb1);
            __syncthreads();
        }
    }

    // ---- epilogue ----
#pragma unroll
    for (int mt = 0; mt < 2; mt++) {
#pragma unroll
        for (int nt = 0; nt < 4; nt++) {
            int r = bm + wm * 32 + mt * 16 + (lane >> 2);
            int c = bn + wn * 32 + nt * 8 + (lane & 3) * 2;
            float2 v0 = make_float2(acc[mt][nt][0], acc[mt][nt][1]);
            float2 v1 = make_float2(acc[mt][nt][2], acc[mt][nt][3]);
            *(float2*)(C + (size_t)r * DD + c)       = v0;
            *(float2*)(C + (size_t)(r + 8) * DD + c) = v1;
        }
    }
}

// ---------------------------------------------------------------------------
// Flash-style causal attention (fp32) — unchanged from R1 (known correct).
// ---------------------------------------------------------------------------
#define AQ 64
#define AKV 64

#define OFF_Q   0
#define OFF_K   (OFF_Q + HD * (AQ + 4))
#define OFF_V   (OFF_K + HD * (AKV + 4))
#define OFF_S   (OFF_V + AKV * (HD + 4))
#define OFF_M   (OFF_S + AQ * (AKV + 1))
#define OFF_L   (OFF_M + AQ)
#define OFF_SC  (OFF_L + AQ)
#define ATTN_SMEM_FLOATS (OFF_SC + AQ)
#define ATTN_SMEM_BYTES  (ATTN_SMEM_FLOATS * 4)

__global__ __launch_bounds__(256)
void attn_kernel(const float* __restrict__ Q,
                 const float* __restrict__ Kk,
                 const float* __restrict__ V,
                 float* __restrict__ O)
{
    extern __shared__ float smem[];
    float* sQ  = smem + OFF_Q;
    float* sK  = smem + OFF_K;
    float* sV  = smem + OFF_V;
    float* sS  = smem + OFF_S;
    float* sm  = smem + OFF_M;
    float* sl  = smem + OFF_L;
    float* ssc = smem + OFF_SC;

    const int qb = blockIdx.x;
    const int bh = blockIdx.y;
    const int b  = bh / HH;
    const int h  = bh % HH;
    const size_t base = (size_t)b * SS * DD + (size_t)h * HD;

    const int tid = threadIdx.x;
    const int tx  = tid & 15;
    const int ty  = tid >> 4;

    {
        int row = tid >> 2;
#pragma unroll
        for (int p = 0; p < 4; p++) {
            int col = (tid & 3) * 4 + p * 16;
            float4 v = *(const float4*)(Q + base + (size_t)(qb * AQ + row) * DD + col);
            sQ[(col + 0) * (AQ + 4) + row] = v.x;
            sQ[(col + 1) * (AQ + 4) + row] = v.y;
            sQ[(col + 2) * (AQ + 4) + row] = v.z;
            sQ[(col + 3) * (AQ + 4) + row] = v.w;
        }
    }
    if (tid < AQ) { sm[tid] = -INFINITY; sl[tid] = 0.f; }

    float oacc[4][4];
#pragma unroll
    for (int i = 0; i < 4; i++)
#pragma unroll
        for (int j = 0; j < 4; j++) oacc[i][j] = 0.f;

    __syncthreads();

    for (int jb = 0; jb <= qb; jb++) {
        {
            int row = tid >> 2;
#pragma unroll
            for (int p = 0; p < 4; p++) {
                int col = (tid & 3) * 4 + p * 16;
                float4 kv4 = *(const float4*)(Kk + base + (size_t)(jb * AKV + row) * DD + col);
                sK[(col + 0) * (AKV + 4) + row] = kv4.x;
                sK[(col + 1) * (AKV + 4) + row] = kv4.y;
                sK[(col + 2) * (AKV + 4) + row] = kv4.z;
                sK[(col + 3) * (AKV + 4) + row] = kv4.w;
                float4 vv4 = *(const float4*)(V + base + (size_t)(jb * AKV + row) * DD + col);
                *(float4*)&sV[row * (HD + 4) + col] = vv4;
            }
        }
        __syncthreads();

        float s[4][4];
#pragma unroll
        for (int i = 0; i < 4; i++)
#pragma unroll
            for (int j = 0; j < 4; j++) s[i][j] = 0.f;

        for (int d0 = 0; d0 < HD; d0++) {
            float4 aq = *(const float4*)&sQ[d0 * (AQ + 4) + ty * 4];
            float4 bk = *(const float4*)&sK[d0 * (AKV + 4) + tx * 4];
            float ar[4] = {aq.x, aq.y, aq.z, aq.w};
            float br[4] = {bk.x, bk.y, bk.z, bk.w};
#pragma unroll
            for (int i = 0; i < 4; i++)
#pragma unroll
                for (int j = 0; j < 4; j++)
                    s[i][j] = fmaf(ar[i], br[j], s[i][j]);
        }
        const float scale = 0.125f;
#pragma unroll
        for (int i = 0; i < 4; i++) {
            int qg = qb * AQ + ty * 4 + i;
#pragma unroll
            for (int j = 0; j < 4; j++) {
                int kg = jb * AKV + tx * 4 + j;
                float val = s[i][j] * scale;
                if (kg > qg) val = -INFINITY;
                sS[(ty * 4 + i) * (AKV + 1) + (tx * 4 + j)] = val;
            }
        }
        __syncthreads();

        if (tid < AQ) {
            float mold = sm[tid];
            float bmax = -INFINITY;
            float* srow = sS + tid * (AKV + 1);
#pragma unroll 8
            for (int c = 0; c < AKV; c++) bmax = fmaxf(bmax, srow[c]);
            float mnew = fmaxf(mold, bmax);
            float scl  = __expf(mold - mnew);
            float sum  = 0.f;
#pragma unroll 8
            for (int c = 0; c < AKV; c++) {
                float p = __expf(srow[c] - mnew);
                srow[c] = p;
                sum += p;
            }
            sl[tid]  = sl[tid] * scl + sum;
            sm[tid]  = mnew;
            ssc[tid] = scl;
        }
        __syncthreads();

        float scr[4];
#pragma unroll
        for (int i = 0; i < 4; i++) scr[i] = ssc[ty * 4 + i];
#pragma unroll
        for (int i = 0; i < 4; i++)
#pragma unroll
            for (int j = 0; j < 4; j++) oacc[i][j] *= scr[i];

        for (int kv = 0; kv < AKV; kv++) {
            float pr[4];
#pragma unroll
            for (int i = 0; i < 4; i++) pr[i] = sS[(ty * 4 + i) * (AKV + 1) + kv];
            float4 vv = *(const float4*)&sV[kv * (HD + 4) + tx * 4];
            float vr[4] = {vv.x, vv.y, vv.z, vv.w};
#pragma unroll
            for (int i = 0; i < 4; i++)
#pragma unroll
                for (int j = 0; j < 4; j++)
                    oacc[i][j] = fmaf(pr[i], vr[j], oacc[i][j]);
        }
        __syncthreads();
    }

    float linv[4];
#pragma unroll
    for (int i = 0; i < 4; i++) linv[i] = 1.0f / sl[ty * 4 + i];
#pragma unroll
    for (int i = 0; i < 4; i++) {
        int qg = qb * AQ + ty * 4 + i;
        float4 o = make_float4(oacc[i][0] * linv[i], oacc[i][1] * linv[i],
                               oacc[i][2] * linv[i], oacc[i][3] * linv[i]);
        *(float4*)(O + base + (size_t)qg * DD + tx * 4) = o;
    }
}

// ---------------------------------------------------------------------------
// Launch
// ---------------------------------------------------------------------------
extern "C" void kernel_launch(void* const* d_in, const int* in_sizes, int n_in,
                              void* d_out, int out_size)
{
    const float* x  = (const float*)d_in[0];
    const float* wq = (const float*)d_in[1];
    const float* wk = (const float*)d_in[2];
    const float* wv = (const float*)d_in[3];
    const float* wo = (const float*)d_in[4];
    float* out = (float*)d_out;

    float *q, *k, *v, *att;
    cudaGetSymbolAddress((void**)&q,   g_q);
    cudaGetSymbolAddress((void**)&k,   g_k);
    cudaGetSymbolAddress((void**)&v,   g_v);
    cudaGetSymbolAddress((void**)&att, g_attn);

    cudaFuncSetAttribute(gemm_mma, cudaFuncAttributeMaxDynamicSharedMemorySize, GEMM_SMEM);
    cudaFuncSetAttribute(attn_kernel, cudaFuncAttributeMaxDynamicSharedMemorySize,
                         ATTN_SMEM_BYTES);

    dim3 ggrid(MR / 128, DD / 128);   // (64, 8)
    dim3 gblk(512);

    gemm_mma<<<ggrid, gblk, GEMM_SMEM>>>(x, wq, q);
    gemm_mma<<<ggrid, gblk, GEMM_SMEM>>>(x, wk, k);
    gemm_mma<<<ggrid, gblk, GEMM_SMEM>>>(x, wv, v);

    dim3 agrid(SS / AQ, BB * HH);     // (32, 64)
    attn_kernel<<<agrid, 256, ATTN_SMEM_BYTES>>>(q, k, v, att);

    gemm_mma<<<ggrid, gblk, GEMM_SMEM>>>(att, wo, out);
}

// round 4
// speedup vs baseline: 2.1109x; 1.4891x over previous
#include <cuda_runtime.h>
#include <cuda_bf16.h>
#include <math.h>
#include <stdint.h>

// Problem constants
#define BB   4
#define SS   2048
#define DD   1024
#define HH   16
#define HD   64
#define MR   (BB * SS)          // 8192 rows

// ---------------------------------------------------------------------------
// Scratch (device globals; no allocation allowed)
// ---------------------------------------------------------------------------
__device__ float g_q[8388608];      // [MR, DD]
__device__ float g_k[8388608];
__device__ float g_v[8388608];
__device__ float g_attn[8388608];

// ---------------------------------------------------------------------------
// Warp-MMA helpers (plain sm_103-legal PTX: ldmatrix + mma.sync, sm_80+)
// ---------------------------------------------------------------------------
__device__ __forceinline__ uint32_t smem_u32(const void* p) {
    uint32_t a;
    asm("{ .reg .u64 t; cvta.to.shared.u64 t, %1; cvt.u32.u64 %0, t; }" : "=r"(a) : "l"(p));
    return a;
}

__device__ __forceinline__ void ldmx4(uint32_t* r, uint32_t addr) {
    asm volatile("ldmatrix.sync.aligned.m8n8.x4.shared.b16 {%0,%1,%2,%3}, [%4];"
                 : "=r"(r[0]), "=r"(r[1]), "=r"(r[2]), "=r"(r[3]) : "r"(addr));
}

__device__ __forceinline__ void mma_bf16(float* c, const uint32_t* a,
                                         uint32_t b0, uint32_t b1) {
    asm volatile(
        "mma.sync.aligned.m16n8k16.row.col.f32.bf16.bf16.f32 "
        "{%0,%1,%2,%3}, {%4,%5,%6,%7}, {%8,%9}, {%0,%1,%2,%3};"
        : "+f"(c[0]), "+f"(c[1]), "+f"(c[2]), "+f"(c[3])
        : "r"(a[0]), "r"(a[1]), "r"(a[2]), "r"(a[3]), "r"(b0), "r"(b1));
}

__device__ __forceinline__ uint32_t pack_bf16(float x, float y) {
    __nv_bfloat162 t = __floats2bfloat162_rn(x, y);
    return *reinterpret_cast<uint32_t*>(&t);
}

// ---------------------------------------------------------------------------
// Split-bf16 HMMA GEMM (unchanged from R3 — passed at 1.4e-5)
// ---------------------------------------------------------------------------
#define BKP 40
#define TILE_E  (128 * BKP)
#define STAGE_E (4 * TILE_E)
#define GEMM_SMEM (2 * STAGE_E * 2)

__device__ __forceinline__ void split4(__nv_bfloat16* hi, __nv_bfloat16* lo, float4 v) {
    __nv_bfloat162 h01 = __floats2bfloat162_rn(v.x, v.y);
    __nv_bfloat162 h23 = __floats2bfloat162_rn(v.z, v.w);
    __nv_bfloat162 l01 = __floats2bfloat162_rn(v.x - __bfloat162float(h01.x),
                                               v.y - __bfloat162float(h01.y));
    __nv_bfloat162 l23 = __floats2bfloat162_rn(v.z - __bfloat162float(h23.x),
                                               v.w - __bfloat162float(h23.y));
    *reinterpret_cast<__nv_bfloat162*>(hi)     = h01;
    *reinterpret_cast<__nv_bfloat162*>(hi + 2) = h23;
    *reinterpret_cast<__nv_bfloat162*>(lo)     = l01;
    *reinterpret_cast<__nv_bfloat162*>(lo + 2) = l23;
}

__global__ __launch_bounds__(512)
void gemm_mma(const float* __restrict__ A, const float* __restrict__ Bw,
              float* __restrict__ C)
{
    extern __shared__ __align__(16) char smem_raw[];
    __nv_bfloat16* sm = reinterpret_cast<__nv_bfloat16*>(smem_raw);

    const int tid  = threadIdx.x;
    const int lane = tid & 31;
    const int wid  = tid >> 5;
    const int wm   = wid >> 2;
    const int wn   = wid & 3;
    const int bm   = blockIdx.x * 128;
    const int bn   = blockIdx.y * 128;

    const int lr = tid >> 2;
    const int lc = (tid & 3) * 8;
    const float* Ag = A  + (size_t)(bm + lr) * DD + lc;
    const float* Bg = Bw + (size_t)(bn + lr) * DD + lc;

    float4 ra0, ra1, rb0, rb1;

    const uint32_t aoffB =
        (uint32_t)(((wm * 32 + (lane & 15)) * BKP + (lane >> 4) * 8) * 2);
    const uint32_t boffB =
        (uint32_t)(((wn * 32 + ((lane >> 4) << 3) + (lane & 7)) * BKP +
                    ((lane >> 3) & 1) * 8) * 2);

    const uint32_t smem_base = smem_u32(sm);

    float acc[2][4][4];
#pragma unroll
    for (int mt = 0; mt < 2; mt++)
#pragma unroll
        for (int nt = 0; nt < 4; nt++)
#pragma unroll
            for (int i = 0; i < 4; i++) acc[mt][nt][i] = 0.f;

    {
        const float* a = Ag; const float* b = Bg;
        ra0 = *(const float4*)a;       ra1 = *(const float4*)(a + 4);
        rb0 = *(const float4*)b;       rb1 = *(const float4*)(b + 4);
        __nv_bfloat16* s = sm;
        int o = lr * BKP + lc;
        split4(s + o,              s + TILE_E + o,     ra0);
        split4(s + o + 4,          s + TILE_E + o + 4, ra1);
        split4(s + 2*TILE_E + o,   s + 3*TILE_E + o,     rb0);
        split4(s + 2*TILE_E + o+4, s + 3*TILE_E + o + 4, rb1);
    }
    __syncthreads();

#pragma unroll 1
    for (int kt = 0; kt < 32; kt++) {
        const int buf = kt & 1;
        if (kt + 1 < 32) {
            const float* a = Ag + (kt + 1) * 32;
            const float* b = Bg + (kt + 1) * 32;
            ra0 = *(const float4*)a;   ra1 = *(const float4*)(a + 4);
            rb0 = *(const float4*)b;   rb1 = *(const float4*)(b + 4);
        }

        const uint32_t tA_h = smem_base + buf * STAGE_E * 2;
        const uint32_t tA_l = tA_h + TILE_E * 2;
        const uint32_t tB_h = tA_h + 2 * TILE_E * 2;
        const uint32_t tB_l = tA_h + 3 * TILE_E * 2;
#pragma unroll
        for (int ks = 0; ks < 2; ks++) {
            const uint32_t kb = ks * 32;
            uint32_t ah[2][4], al[2][4], bh[2][4], bl[2][4];
#pragma unroll
            for (int mt = 0; mt < 2; mt++) {
                ldmx4(ah[mt], tA_h + aoffB + mt * (16 * BKP * 2) + kb);
                ldmx4(al[mt], tA_l + aoffB + mt * (16 * BKP * 2) + kb);
            }
#pragma unroll
            for (int nt2 = 0; nt2 < 2; nt2++) {
                ldmx4(bh[nt2], tB_h + boffB + nt2 * (16 * BKP * 2) + kb);
                ldmx4(bl[nt2], tB_l + boffB + nt2 * (16 * BKP * 2) + kb);
            }
#pragma unroll
            for (int mt = 0; mt < 2; mt++) {
#pragma unroll
                for (int nt2 = 0; nt2 < 2; nt2++) {
#pragma unroll
                    for (int h = 0; h < 2; h++) {
                        float* c = acc[mt][nt2 * 2 + h];
                        uint32_t b0h = bh[nt2][h * 2], b1h = bh[nt2][h * 2 + 1];
                        uint32_t b0l = bl[nt2][h * 2], b1l = bl[nt2][h * 2 + 1];
                        mma_bf16(c, ah[mt], b0h, b1h);
                        mma_bf16(c, ah[mt], b0l, b1l);
                        mma_bf16(c, al[mt], b0h, b1h);
                    }
                }
            }
        }

        if (kt + 1 < 32) {
            __nv_bfloat16* s = sm + (1 - buf) * STAGE_E;
            int o = lr * BKP + lc;
            split4(s + o,              s + TILE_E + o,     ra0);
            split4(s + o + 4,          s + TILE_E + o + 4, ra1);
            split4(s + 2*TILE_E + o,   s + 3*TILE_E + o,     rb0);
            split4(s + 2*TILE_E + o+4, s + 3*TILE_E + o + 4, rb1);
            __syncthreads();
        }
    }

#pragma unroll
    for (int mt = 0; mt < 2; mt++) {
#pragma unroll
        for (int nt = 0; nt < 4; nt++) {
            int r = bm + wm * 32 + mt * 16 + (lane >> 2);
            int c = bn + wn * 32 + nt * 8 + (lane & 3) * 2;
            float2 v0 = make_float2(acc[mt][nt][0], acc[mt][nt][1]);
            float2 v1 = make_float2(acc[mt][nt][2], acc[mt][nt][3]);
            *(float2*)(C + (size_t)r * DD + c)       = v0;
            *(float2*)(C + (size_t)(r + 8) * DD + c) = v1;
        }
    }
}

// ---------------------------------------------------------------------------
// Split-bf16 HMMA flash attention.
// CTA: 64 q-rows of one (b,h); 128 threads = 4 warps, warp owns 16 q rows.
// KV tiles of 64. S = QhKh + QlKh + QhKl; O += PhVh + PlVh + PhVl.
// smem tiles stride 72 bf16 (144B rows, ldmatrix-friendly).
// ---------------------------------------------------------------------------
#define AP 72                         // padded row stride (bf16 elems)
#define AT (64 * AP)                  // 4608 bf16 = 9216 B per tile
// layout: Qh, Ql, Kh, Kl, Vh, Vl
#define ATTN_SMEM_BYTES (6 * AT * 2)  // 55296

__global__ __launch_bounds__(128)
void attn_mma(const float* __restrict__ Q,
              const float* __restrict__ Kk,
              const float* __restrict__ V,
              float* __restrict__ O)
{
    extern __shared__ __align__(16) char asm_raw[];
    __nv_bfloat16* sQh = reinterpret_cast<__nv_bfloat16*>(asm_raw);
    __nv_bfloat16* sQl = sQh + AT;
    __nv_bfloat16* sKh = sQh + 2 * AT;
    __nv_bfloat16* sKl = sQh + 3 * AT;
    __nv_bfloat16* sVh = sQh + 4 * AT;   // TRANSPOSED: [hd][kv]
    __nv_bfloat16* sVl = sQh + 5 * AT;

    const uint32_t sb   = smem_u32(sQh);
    const uint32_t uQh  = sb;
    const uint32_t uQl  = sb + AT * 2;
    const uint32_t uKh  = sb + 2 * AT * 2;
    const uint32_t uKl  = sb + 3 * AT * 2;
    const uint32_t uVh  = sb + 4 * AT * 2;
    const uint32_t uVl  = sb + 5 * AT * 2;

    const int qb = blockIdx.x;            // 0..31
    const int bh = blockIdx.y;            // 0..63
    const int b  = bh / HH;
    const int h  = bh % HH;
    const size_t base = (size_t)b * SS * DD + (size_t)h * HD;

    const int tid  = threadIdx.x;
    const int lane = tid & 31;
    const int w    = tid >> 5;            // warp 0..3 -> q rows w*16..+15

    // ---- load Q (64 x 64) once: 2 threads/row, 32 floats each ----
    {
        int lr = tid >> 1, lcq = (tid & 1) * 32;
        const float* gq = Q + base + (size_t)(qb * 64 + lr) * DD + lcq;
        int o = lr * AP + lcq;
#pragma unroll
        for (int i = 0; i < 8; i++) {
            float4 v = *(const float4*)(gq + i * 4);
            split4(sQh + o + i * 4, sQl + o + i * 4, v);
        }
    }

    // fragment addresses
    const uint32_t aoff =                 // A (Q rows w*16..): m16k16
        (uint32_t)(((w * 16 + (lane & 15)) * AP + (lane >> 4) * 8) * 2);
    const uint32_t boff =                 // B (16 n rows per pair): n16k16
        (uint32_t)(((((lane >> 4) << 3) + (lane & 7)) * AP + ((lane >> 3) & 1) * 8) * 2);

    const int r0 = lane >> 2;             // local row within warp's 16
    const int qg0 = qb * 64 + w * 16 + r0;
    const int qg1 = qg0 + 8;

    float m0 = -INFINITY, m1 = -INFINITY, l0 = 0.f, l1 = 0.f;
    float oacc[8][4];
#pragma unroll
    for (int nt = 0; nt < 8; nt++)
#pragma unroll
        for (int i = 0; i < 4; i++) oacc[nt][i] = 0.f;

    __syncthreads();

#pragma unroll 1
    for (int jb = 0; jb <= qb; jb++) {
        // ---- load K tile [kv][hd] ----
        {
            int lr = tid >> 1, lck = (tid & 1) * 32;
            const float* gk = Kk + base + (size_t)(jb * 64 + lr) * DD + lck;
            int o = lr * AP + lck;
#pragma unroll
            for (int i = 0; i < 8; i++) {
                float4 v = *(const float4*)(gk + i * 4);
                split4(sKh + o + i * 4, sKl + o + i * 4, v);
            }
        }
        // ---- load V tile transposed -> sVt[hd][kv] ----
        {
            int kvc = tid >> 3;           // 0..15 (4 kv rows each)
            int hdc = tid & 7;            // 0..7  (8 hd each)
            float va[4][8];
#pragma unroll
            for (int j = 0; j < 4; j++) {
                const float* gv = V + base + (size_t)(jb * 64 + kvc * 4 + j) * DD + hdc * 8;
                float4 v0 = *(const float4*)gv;
                float4 v1 = *(const float4*)(gv + 4);
                va[j][0] = v0.x; va[j][1] = v0.y; va[j][2] = v0.z; va[j][3] = v0.w;
                va[j][4] = v1.x; va[j][5] = v1.y; va[j][6] = v1.z; va[j][7] = v1.w;
            }
#pragma unroll
            for (int i = 0; i < 8; i++) {
                __nv_bfloat16 hh[4], ll[4];
#pragma unroll
                for (int j = 0; j < 4; j++) {
                    hh[j] = __float2bfloat16_rn(va[j][i]);
                    ll[j] = __float2bfloat16_rn(va[j][i] - __bfloat162float(hh[j]));
                }
                int o = (hdc * 8 + i) * AP + kvc * 4;
                *reinterpret_cast<uint2*>(sVh + o) = *reinterpret_cast<uint2*>(hh);
                *reinterpret_cast<uint2*>(sVl + o) = *reinterpret_cast<uint2*>(ll);
            }
        }
        __syncthreads();

        // ---- S = Q K^T (split bf16) ----
        float sacc[8][4];
#pragma unroll
        for (int nt = 0; nt < 8; nt++)
#pragma unroll
            for (int i = 0; i < 4; i++) sacc[nt][i] = 0.f;

#pragma unroll
        for (int kk = 0; kk < 4; kk++) {       // hd in chunks of 16
            const uint32_t kb = kk * 32;       // bytes
            uint32_t qh[4], ql[4];
            ldmx4(qh, uQh + aoff + kb);
            ldmx4(ql, uQl + aoff + kb);
#pragma unroll
            for (int np = 0; np < 4; np++) {   // kv n-pairs of 16
                const uint32_t nb = (uint32_t)(np * 16 * AP * 2);
                uint32_t kh[4], kl[4];
                ldmx4(kh, uKh + boff + nb + kb);
                ldmx4(kl, uKl + boff + nb + kb);
#pragma unroll
                for (int hh = 0; hh < 2; hh++) {
                    float* c = sacc[np * 2 + hh];
                    mma_bf16(c, qh, kh[hh * 2], kh[hh * 2 + 1]);
                    mma_bf16(c, ql, kh[hh * 2], kh[hh * 2 + 1]);
                    mma_bf16(c, qh, kl[hh * 2], kl[hh * 2 + 1]);
                }
            }
        }

        // ---- mask + online softmax (registers + quad shuffles) ----
        const float scale = 0.125f;
        const int kvb = jb * 64 + (lane & 3) * 2;
        float mx0 = -INFINITY, mx1 = -INFINITY;
#pragma unroll
        for (int nt = 0; nt < 8; nt++) {
            int kg = kvb + nt * 8;
            float s0 = sacc[nt][0] * scale; if (kg     > qg0) s0 = -INFINITY;
            float s1 = sacc[nt][1] * scale; if (kg + 1 > qg0) s1 = -INFINITY;
            float s2 = sacc[nt][2] * scale; if (kg     > qg1) s2 = -INFINITY;
            float s3 = sacc[nt][3] * scale; if (kg + 1 > qg1) s3 = -INFINITY;
            sacc[nt][0] = s0; sacc[nt][1] = s1; sacc[nt][2] = s2; sacc[nt][3] = s3;
            mx0 = fmaxf(mx0, fmaxf(s0, s1));
            mx1 = fmaxf(mx1, fmaxf(s2, s3));
        }
        mx0 = fmaxf(mx0, __shfl_xor_sync(0xffffffff, mx0, 1));
        mx0 = fmaxf(mx0, __shfl_xor_sync(0xffffffff, mx0, 2));
        mx1 = fmaxf(mx1, __shfl_xor_sync(0xffffffff, mx1, 1));
        mx1 = fmaxf(mx1, __shfl_xor_sync(0xffffffff, mx1, 2));

        float mn0 = fmaxf(m0, mx0), mn1 = fmaxf(m1, mx1);
        float sc0 = __expf(m0 - mn0), sc1 = __expf(m1 - mn1);
        float sum0 = 0.f, sum1 = 0.f;
#pragma unroll
        for (int nt = 0; nt < 8; nt++) {
            float p0 = __expf(sacc[nt][0] - mn0);
            float p1 = __expf(sacc[nt][1] - mn0);
            float p2 = __expf(sacc[nt][2] - mn1);
            float p3 = __expf(sacc[nt][3] - mn1);
            sacc[nt][0] = p0; sacc[nt][1] = p1; sacc[nt][2] = p2; sacc[nt][3] = p3;
            sum0 += p0 + p1; sum1 += p2 + p3;
        }
        sum0 += __shfl_xor_sync(0xffffffff, sum0, 1);
        sum0 += __shfl_xor_sync(0xffffffff, sum0, 2);
        sum1 += __shfl_xor_sync(0xffffffff, sum1, 1);
        sum1 += __shfl_xor_sync(0xffffffff, sum1, 2);
        l0 = l0 * sc0 + sum0;  l1 = l1 * sc1 + sum1;
        m0 = mn0;              m1 = mn1;

#pragma unroll
        for (int nt = 0; nt < 8; nt++) {
            oacc[nt][0] *= sc0; oacc[nt][1] *= sc0;
            oacc[nt][2] *= sc1; oacc[nt][3] *= sc1;
        }

        // ---- O += P V (split bf16), P fragments from sacc ----
#pragma unroll
        for (int t = 0; t < 4; t++) {          // kv in chunks of 16
            uint32_t ph[4], pl[4];
            {
                float p00 = sacc[2*t][0],   p01 = sacc[2*t][1];
                float p02 = sacc[2*t][2],   p03 = sacc[2*t][3];
                float p10 = sacc[2*t+1][0], p11 = sacc[2*t+1][1];
                float p12 = sacc[2*t+1][2], p13 = sacc[2*t+1][3];
                ph[0] = pack_bf16(p00, p01);
                ph[1] = pack_bf16(p02, p03);
                ph[2] = pack_bf16(p10, p11);
                ph[3] = pack_bf16(p12, p13);
                __nv_bfloat162* hp = reinterpret_cast<__nv_bfloat162*>(ph);
                pl[0] = pack_bf16(p00 - __bfloat162float(hp[0].x), p01 - __bfloat162float(hp[0].y));
                pl[1] = pack_bf16(p02 - __bfloat162float(hp[1].x), p03 - __bfloat162float(hp[1].y));
                pl[2] = pack_bf16(p10 - __bfloat162float(hp[2].x), p11 - __bfloat162float(hp[2].y));
                pl[3] = pack_bf16(p12 - __bfloat162float(hp[3].x), p13 - __bfloat162float(hp[3].y));
            }
            const uint32_t kb = t * 32;        // k (kv) byte offset
#pragma unroll
            for (int np = 0; np < 4; np++) {   // hd n-pairs of 16
                const uint32_t nb = (uint32_t)(np * 16 * AP * 2);
                uint32_t vh[4], vl[4];
                ldmx4(vh, uVh + boff + nb + kb);
                ldmx4(vl, uVl + boff + nb + kb);
#pragma unroll
                for (int hh = 0; hh < 2; hh++) {
                    float* c = oacc[np * 2 + hh];
                    mma_bf16(c, ph, vh[hh * 2], vh[hh * 2 + 1]);
                    mma_bf16(c, pl, vh[hh * 2], vh[hh * 2 + 1]);
                    mma_bf16(c, ph, vl[hh * 2], vl[hh * 2 + 1]);
                }
            }
        }
        __syncthreads();   // protect K/V tiles before next iteration overwrites
    }

    // ---- epilogue ----
    float li0 = 1.0f / l0, li1 = 1.0f / l1;
    const int col0 = (lane & 3) * 2;
#pragma unroll
    for (int nt = 0; nt < 8; nt++) {
        int c = nt * 8 + col0;
        float* o0 = O + base + (size_t)qg0 * DD + c;
        float* o1 = O + base + (size_t)qg1 * DD + c;
        *(float2*)o0 = make_float2(oacc[nt][0] * li0, oacc[nt][1] * li0);
        *(float2*)o1 = make_float2(oacc[nt][2] * li1, oacc[nt][3] * li1);
    }
}

// ---------------------------------------------------------------------------
// Launch
// ---------------------------------------------------------------------------
extern "C" void kernel_launch(void* const* d_in, const int* in_sizes, int n_in,
                              void* d_out, int out_size)
{
    const float* x  = (const float*)d_in[0];
    const float* wq = (const float*)d_in[1];
    const float* wk = (const float*)d_in[2];
    const float* wv = (const float*)d_in[3];
    const float* wo = (const float*)d_in[4];
    float* out = (float*)d_out;

    float *q, *k, *v, *att;
    cudaGetSymbolAddress((void**)&q,   g_q);
    cudaGetSymbolAddress((void**)&k,   g_k);
    cudaGetSymbolAddress((void**)&v,   g_v);
    cudaGetSymbolAddress((void**)&att, g_attn);

    cudaFuncSetAttribute(gemm_mma, cudaFuncAttributeMaxDynamicSharedMemorySize, GEMM_SMEM);
    cudaFuncSetAttribute(attn_mma, cudaFuncAttributeMaxDynamicSharedMemorySize,
                         ATTN_SMEM_BYTES);

    dim3 ggrid(MR / 128, DD / 128);   // (64, 8)
    dim3 gblk(512);

    gemm_mma<<<ggrid, gblk, GEMM_SMEM>>>(x, wq, q);
    gemm_mma<<<ggrid, gblk, GEMM_SMEM>>>(x, wk, k);
    gemm_mma<<<ggrid, gblk, GEMM_SMEM>>>(x, wv, v);

    dim3 agrid(SS / 64, BB * HH);     // (32, 64)
    attn_mma<<<agrid, 128, ATTN_SMEM_BYTES>>>(q, k, v, att);

    gemm_mma<<<ggrid, gblk, GEMM_SMEM>>>(att, wo, out);
}